// round 15
// baseline (speedup 1.0000x reference)
#include <cuda_runtime.h>
#include <cuda_bf16.h>
#include <math.h>
#include <stdint.h>

#define Bz 32
#define NS 4096
#define Dm 256
#define Hh 4
#define DH 64
#define Ll 6
#define NQ 512
#define NK 1024
#define ATT_SCALE 0.125f

// ---------------- scratch ----------------
__device__ float g_upd[(size_t)Bz * NS * Dm];
__device__ float g_h  [(size_t)Bz * NQ * Dm];
__device__ uint32_t g_mbits[(size_t)Ll * NQ * (NK / 32)];
__device__ unsigned char g_img_qn [(size_t)128 * 8 * 16384];
__device__ unsigned char g_img_kn [(size_t)256 * 8 * 16384];
__device__ unsigned char g_img_Q  [(size_t)128 * 8 * 16384];
__device__ unsigned char g_img_K  [(size_t)256 * 8 * 16384];
__device__ unsigned char g_img_ctx[(size_t)128 * 8 * 16384];
__device__ unsigned char g_img_h  [(size_t)128 * 8 * 16384];
__device__ unsigned char g_img_t  [(size_t)128 * 8 * 16384];
__device__ unsigned char g_img_Vt [(size_t)256 * 16 * 8192];
__device__ __nv_bfloat16 g_wprep[(size_t)6 * 12 * 256 * 64];

__device__ __forceinline__ size_t img_off(int tile, int g, int hilo) {
    return (((size_t)tile * 4 + g) * 2 + hilo) << 14;
}
__device__ __forceinline__ size_t imgv_off(int tile, int h, int half, int hilo) {
    return ((((size_t)tile * 4 + h) * 2 + half) * 2 + hilo) << 13;
}

// ---------------- small helpers ----------------
__device__ __forceinline__ uint32_t smem_u32(const void* p) {
    uint32_t a;
    asm("{ .reg .u64 t; cvta.to.shared.u64 t, %1; cvt.u32.u64 %0, t; }" : "=r"(a) : "l"(p));
    return a;
}
__device__ __forceinline__ unsigned short f2bf(float x) {
    __nv_bfloat16 b = __float2bfloat16_rn(x);
    return *reinterpret_cast<unsigned short*>(&b);
}
__device__ __forceinline__ unsigned short f2bf_lo(float x) {
    __nv_bfloat16 b = __float2bfloat16_rn(x);
    float hi = __bfloat162float(b);
    __nv_bfloat16 l = __float2bfloat16_rn(x - hi);
    return *reinterpret_cast<unsigned short*>(&l);
}
__device__ __forceinline__ uint32_t pack2(unsigned short a, unsigned short b) {
    return (uint32_t)a | ((uint32_t)b << 16);
}
#define CVT2(res, a, b) asm("cvt.rn.bf16x2.f32 %0, %1, %2;" : "=r"(res) : "f"(b), "f"(a))

__device__ __forceinline__ void packhilo(float x0, float x1, uint32_t& hi, uint32_t& lo) {
    CVT2(hi, x0, x1);
    float h0 = __uint_as_float(hi << 16);
    float h1 = __uint_as_float(hi & 0xFFFF0000u);
    CVT2(lo, x0 - h0, x1 - h1);
}

__device__ __forceinline__ float gelu_tanh(float x) {
    const float c = 0.7978845608028654f;
    float t = tanhf(c * (x + 0.044715f * x * x * x));
    return 0.5f * x * (1.0f + t);
}

// ---------------- mbarrier / bulk-copy plumbing ----------------
#define MBAR_INIT(addr, cnt) \
    asm volatile("mbarrier.init.shared.b64 [%0], %1;" :: "r"(addr), "r"(cnt) : "memory")
#define MBAR_INVAL(addr) \
    asm volatile("mbarrier.inval.shared.b64 [%0];" :: "r"(addr) : "memory")
#define MBAR_EXPECT(addr, bytes) \
    asm volatile("mbarrier.arrive.expect_tx.shared.b64 _, [%0], %1;" :: "r"(addr), "r"(bytes) : "memory")
#define MBAR_WAIT(addr, par) do { \
    uint32_t _m = (addr); uint32_t _p = (par); uint32_t _d; \
    asm volatile("{\n\t.reg .pred p;\n\t" \
        "mbarrier.try_wait.parity.acquire.cta.shared::cta.b64 p, [%1], %2;\n\t" \
        "selp.b32 %0, 1, 0, p;\n\t}" : "=r"(_d) : "r"(_m), "r"(_p) : "memory"); \
    if (!_d) { \
        asm volatile("{\n\t.reg .pred P1;\n\t" \
            "W_%=:\n\t" \
            "mbarrier.try_wait.parity.acquire.cta.shared::cta.b64 P1, [%0], %1, 0x989680;\n\t" \
            "@P1 bra.uni D_%=;\n\t" \
            "bra.uni W_%=;\n\t" \
            "D_%=:\n\t}" :: "r"(_m), "r"(_p) : "memory"); \
    } } while (0)

__device__ __forceinline__ void bulk_cp(uint32_t dst, const void* src, uint32_t bytes,
                                        uint32_t mbar) {
    asm volatile(
        "cp.async.bulk.shared::cta.global.mbarrier::complete_tx::bytes [%0], [%1], %2, [%3];"
        :: "r"(dst), "l"(src), "r"(bytes), "r"(mbar) : "memory");
}

#if defined(__CUDA_ARCH_FEAT_SM103_ALL)
#define TC_ALLOC(sa, n) \
    asm volatile("tcgen05.alloc.cta_group::1.sync.aligned.shared::cta.b32 [%0], %1;" \
        :: "r"(sa), "r"(n) : "memory")
#define TC_RELINQ() \
    asm volatile("tcgen05.relinquish_alloc_permit.cta_group::1.sync.aligned;")
#define TC_DEALLOC(t, n) \
    asm volatile("tcgen05.dealloc.cta_group::1.sync.aligned.b32 %0, %1;" :: "r"(t), "r"(n))
#define TC_COMMIT(mb) \
    asm volatile("tcgen05.commit.cta_group::1.mbarrier::arrive::one.shared::cluster.b64 [%0];" \
        :: "r"(mb) : "memory")
#define TC_FENCE_AFTER() asm volatile("tcgen05.fence::after_thread_sync;" ::: "memory")
#define TC_FENCE_BEFORE() asm volatile("tcgen05.fence::before_thread_sync;" ::: "memory")
#define TC_WAIT_LD() asm volatile("tcgen05.wait::ld.sync.aligned;" ::: "memory")
#define TC_WAIT_ST() asm volatile("tcgen05.wait::st.sync.aligned;" ::: "memory")

#define TC_LD_X32(r, ta) \
    asm volatile("tcgen05.ld.sync.aligned.32x32b.x32.b32 " \
        "{%0, %1, %2, %3, %4, %5, %6, %7, %8, %9, %10, %11, %12, %13, %14, %15, " \
        "%16, %17, %18, %19, %20, %21, %22, %23, %24, %25, %26, %27, %28, %29, %30, %31}, [%32];" \
        : "=r"((r)[0]), "=r"((r)[1]), "=r"((r)[2]), "=r"((r)[3]), \
          "=r"((r)[4]), "=r"((r)[5]), "=r"((r)[6]), "=r"((r)[7]), \
          "=r"((r)[8]), "=r"((r)[9]), "=r"((r)[10]), "=r"((r)[11]), \
          "=r"((r)[12]), "=r"((r)[13]), "=r"((r)[14]), "=r"((r)[15]), \
          "=r"((r)[16]), "=r"((r)[17]), "=r"((r)[18]), "=r"((r)[19]), \
          "=r"((r)[20]), "=r"((r)[21]), "=r"((r)[22]), "=r"((r)[23]), \
          "=r"((r)[24]), "=r"((r)[25]), "=r"((r)[26]), "=r"((r)[27]), \
          "=r"((r)[28]), "=r"((r)[29]), "=r"((r)[30]), "=r"((r)[31]) \
        : "r"(ta))

#define TC_ST_X32(ta, r) \
    asm volatile("tcgen05.st.sync.aligned.32x32b.x32.b32 [%0], " \
        "{%1, %2, %3, %4, %5, %6, %7, %8, %9, %10, %11, %12, %13, %14, %15, %16, " \
        "%17, %18, %19, %20, %21, %22, %23, %24, %25, %26, %27, %28, %29, %30, %31, %32};" \
        :: "r"(ta), \
           "r"((r)[0]), "r"((r)[1]), "r"((r)[2]), "r"((r)[3]), \
           "r"((r)[4]), "r"((r)[5]), "r"((r)[6]), "r"((r)[7]), \
           "r"((r)[8]), "r"((r)[9]), "r"((r)[10]), "r"((r)[11]), \
           "r"((r)[12]), "r"((r)[13]), "r"((r)[14]), "r"((r)[15]), \
           "r"((r)[16]), "r"((r)[17]), "r"((r)[18]), "r"((r)[19]), \
           "r"((r)[20]), "r"((r)[21]), "r"((r)[22]), "r"((r)[23]), \
           "r"((r)[24]), "r"((r)[25]), "r"((r)[26]), "r"((r)[27]), \
           "r"((r)[28]), "r"((r)[29]), "r"((r)[30]), "r"((r)[31]) \
        : "memory")

__device__ __forceinline__ void mma_f16_ss(uint32_t d, uint64_t ad, uint64_t bd,
                                           uint32_t idesc, bool acc) {
    uint32_t en = acc ? 1u : 0u;
    asm volatile(
        "{\n\t.reg .pred p;\n\t"
        "setp.ne.u32 p, %5, 0;\n\t"
        "tcgen05.mma.cta_group::1.kind::f16 [%0], %1, %2, %3, {%4, %4, %4, %4}, p;\n\t"
        "}"
        :: "r"(d), "l"(ad), "l"(bd), "r"(idesc), "r"(0u), "r"(en)
        : "memory");
}
__device__ __forceinline__ void mma_f16_ts(uint32_t d, uint32_t a, uint64_t bd,
                                           uint32_t idesc, bool acc) {
    uint32_t en = acc ? 1u : 0u;
    asm volatile(
        "{\n\t.reg .pred p;\n\t"
        "setp.ne.u32 p, %5, 0;\n\t"
        "tcgen05.mma.cta_group::1.kind::f16 [%0], [%1], %2, %3, {%4, %4, %4, %4}, p;\n\t"
        "}"
        :: "r"(d), "r"(a), "l"(bd), "r"(idesc), "r"(0u), "r"(en)
        : "memory");
}
#endif

static constexpr uint64_t DESC_BASE_SW128 =
    (2ull << 61) | (1ull << 46) | (64ull << 32) | (1ull << 16);
__device__ __forceinline__ uint64_t make_desc(uint32_t addr) {
    return DESC_BASE_SW128 | ((uint64_t)(addr >> 4) & 0x3FFF);
}

#define IDESC_N256 ((1u << 4) | (1u << 7) | (1u << 10) | ((256u / 8) << 17) | ((128u / 16) << 24))
#define IDESC_N128 ((1u << 4) | (1u << 7) | (1u << 10) | ((128u / 8) << 17) | ((128u / 16) << 24))
#define IDESC_N64  ((1u << 4) | (1u << 7) | (1u << 10) | ((64u  / 8) << 17) | ((128u / 16) << 24))

#define GT_SMEM_TOTAL (1024 + 3 * 49152)   // 3-stage kernels (wo_ln, ffn2)
#define GT2_SMEM_TOTAL (1024 + 2 * 49152)  // 2-stage kernels (qkv, ffn1): 2 CTAs/SM
#define AT_QHI   2048
#define AT_QLO   18432
#define AT_KHI   34816
#define AT_KLO   51200
#define AT_VHI_A 67584
#define AT_VHI_B 75776
#define AT_VLO_A 83968
#define AT_VLO_B 92160
#define AT_SMEM_TOTAL 100352

// ---------------- prep: weights + mask bits ----------------
__global__ __launch_bounds__(256)
void prep_all_kernel(const float* __restrict__ Wq, const float* __restrict__ Wk,
                     const float* __restrict__ Wv, const float* __restrict__ Wo,
                     const float* __restrict__ W1, const float* __restrict__ W2,
                     __nv_bfloat16* __restrict__ wprep,
                     const float* __restrict__ mask, uint32_t* __restrict__ bits) {
    int bx = blockIdx.x;
    if (bx < 72) {
        int w = bx / 12, c = bx % 12;
        const float* W = (w == 0) ? Wq : (w == 1) ? Wk : (w == 2) ? Wv
                       : (w == 3) ? Wo : (w == 4) ? W1 : W2;
        int g = c / 3, t = c % 3, n = threadIdx.x;
        char* base = (char*)wprep + ((size_t)w * 12 + c) * 32768;
        #pragma unroll 4
        for (int j = 0; j < 64; j += 2) {
            float x0 = W[(size_t)(64 * g + j) * 256 + n];
            float x1 = W[(size_t)(64 * g + j + 1) * 256 + n];
            unsigned short h0 = (t == 2) ? f2bf_lo(x0) : f2bf(x0);
            unsigned short h1 = (t == 2) ? f2bf_lo(x1) : f2bf(x1);
            uint32_t off = n * 128 + j * 2;
            off ^= (off >> 3) & 0x70;
            *(uint32_t*)(base + off) = pack2(h0, h1);
        }
    } else {
        int idx = bx - 72;
        int lev = idx >> 6, rblk = idx & 63;
        int w = threadIdx.x >> 5, l = threadIdx.x & 31;
        int r = rblk * 8 + w;
        const float* row = mask + ((size_t)lev * NQ + r) * NK;
        uint32_t myword = 0;
        for (int j = 0; j < 32; j++) {
            uint32_t bal = __ballot_sync(0xffffffffu, row[j * 32 + l] > 0.5f);
            if (l == j) myword = bal;
        }
        bits[((size_t)lev * NQ + r) * 32 + l] = myword;
    }
}

// ---------------- gather + LN -> images: warp per row ----------------
__global__ __launch_bounds__(256)
void gather_ln_img_kernel(const float* __restrict__ emb, const float* __restrict__ upd,
                          const int* __restrict__ qi, const int* __restrict__ ki,
                          const float* __restrict__ sc, const float* __restrict__ bi,
                          unsigned char* __restrict__ imgq, unsigned char* __restrict__ imgk) {
    int wid = threadIdx.x >> 5, lane = threadIdx.x & 31;
    int i = blockIdx.x * 8 + wid;
    int b = i / (NQ + NK), rr = i % (NQ + NK);
    const int* idx;
    unsigned char* img;
    int r2, nrows;
    if (rr < NQ) { idx = qi; img = imgq; r2 = rr; nrows = NQ; }
    else         { idx = ki; img = imgk; r2 = rr - NQ; nrows = NK; }
    int j = __ldg(&idx[r2]);
    const float* e = emb + (size_t)j * Dm + lane * 8;
    const float* u = upd + ((size_t)b * NS + j) * Dm + lane * 8;
    float4 e0 = *(const float4*)e, e1 = *(const float4*)(e + 4);
    float4 u0 = *(const float4*)u, u1 = *(const float4*)(u + 4);
    float x[8] = {e0.x + u0.x, e0.y + u0.y, e0.z + u0.z, e0.w + u0.w,
                  e1.x + u1.x, e1.y + u1.y, e1.z + u1.z, e1.w + u1.w};
    float s = 0.f, q = 0.f;
    #pragma unroll
    for (int k = 0; k < 8; k++) { s += x[k]; q += x[k] * x[k]; }
    #pragma unroll
    for (int o = 16; o > 0; o >>= 1) {
        s += __shfl_xor_sync(0xffffffffu, s, o);
        q += __shfl_xor_sync(0xffffffffu, q, o);
    }
    float m = s * (1.0f / Dm);
    float var = q * (1.0f / Dm) - m * m;
    float rs = rsqrtf(fmaxf(var, 0.f) + 1e-5f);
    float4 s0 = *(const float4*)(sc + lane * 8), s1 = *(const float4*)(sc + lane * 8 + 4);
    float4 b0 = *(const float4*)(bi + lane * 8), b1 = *(const float4*)(bi + lane * 8 + 4);
    float y[8];
    y[0] = (x[0] - m) * rs * s0.x + b0.x; y[1] = (x[1] - m) * rs * s0.y + b0.y;
    y[2] = (x[2] - m) * rs * s0.z + b0.z; y[3] = (x[3] - m) * rs * s0.w + b0.w;
    y[4] = (x[4] - m) * rs * s1.x + b1.x; y[5] = (x[5] - m) * rs * s1.y + b1.y;
    y[6] = (x[6] - m) * rs * s1.z + b1.z; y[7] = (x[7] - m) * rs * s1.w + b1.w;
    int row = b * nrows + r2;
    int tile = row >> 7, r7 = row & 127;
    int g = lane >> 3;
    uint32_t off = r7 * 128 + ((lane * 8) & 63) * 2;
    off ^= (off >> 3) & 0x70;
    uint4 hv, lv;
    packhilo(y[0], y[1], hv.x, lv.x);
    packhilo(y[2], y[3], hv.y, lv.y);
    packhilo(y[4], y[5], hv.z, lv.z);
    packhilo(y[6], y[7], hv.w, lv.w);
    *(uint4*)(img + img_off(tile, g, 0) + off) = hv;
    *(uint4*)(img + img_off(tile, g, 1) + off) = lv;
}

// ---------------- tc GEMM shared pieces ----------------
__device__ __forceinline__ uint32_t tc_gemm_start(uint32_t sb) {
    uint32_t tmem = 0;
#if defined(__CUDA_ARCH_FEAT_SM103_ALL)
    int tid = threadIdx.x, wid = tid >> 5;
    if (wid == 0) { TC_ALLOC(sb + 0, 256); TC_RELINQ(); }
    if (tid == 0) {
        #pragma unroll
        for (int i = 0; i < 7; i++) MBAR_INIT(sb + 16 + 8 * i, 1);
    }
    __syncthreads();
    asm volatile("ld.shared.b32 %0, [%1];" : "=r"(tmem) : "r"(sb + 0));
#endif
    return tmem;
}

// ST-stage pipelined mainloop (ST = 2 or 3)
template <int ST>
__device__ __forceinline__ void tc_gemm_mainloop(const unsigned char* __restrict__ Aimg,
                                                 const __nv_bfloat16* __restrict__ Wp,
                                                 int tile, uint32_t sb, uint32_t tmem) {
#if defined(__CUDA_ARCH_FEAT_SM103_ALL)
    if (threadIdx.x == 0) {
        auto issue_chunk = [&](int c, int s) {
            int g = c / 3, tt = c % 3;
            int aidx = tile * 8 + g * 2 + (tt == 1 ? 1 : 0);
            uint32_t fm = sb + 16 + 8 * s;
            uint32_t sa = sb + 1024 + s * 49152;
            MBAR_EXPECT(fm, 49152);
            bulk_cp(sa, Aimg + ((size_t)aidx << 14), 16384, fm);
            bulk_cp(sa + 16384, (const unsigned char*)Wp + ((size_t)c << 15), 32768, fm);
        };
        #pragma unroll
        for (int s = 0; s < ST; s++) issue_chunk(s, s);
        int fph[3] = {0, 0, 0}, dph[3] = {0, 0, 0};
        for (int c = 0; c < 12; c++) {
            int s = c % ST;
            MBAR_WAIT(sb + 16 + 8 * s, fph[s]); fph[s] ^= 1;
            uint32_t sa = sb + 1024 + s * 49152;
            uint64_t ad = make_desc(sa);
            uint64_t bd = make_desc(sa + 16384);
            #pragma unroll
            for (int k = 0; k < 4; k++)
                mma_f16_ss(tmem, ad + 2 * k, bd + 2 * k, IDESC_N256, (c > 0) || (k > 0));
            if (c + ST <= 11) {
                TC_COMMIT(sb + 40 + 8 * s);
                MBAR_WAIT(sb + 40 + 8 * s, dph[s]); dph[s] ^= 1;
                issue_chunk(c + ST, s);
            } else if (c == 11) {
                TC_COMMIT(sb + 64);
            }
        }
    }
    MBAR_WAIT(sb + 64, 0);
    TC_FENCE_AFTER();
    __syncthreads();
#endif
}

__device__ __forceinline__ void tc_gemm_end(uint32_t sb, uint32_t tmem) {
#if defined(__CUDA_ARCH_FEAT_SM103_ALL)
    __syncthreads();
    if (threadIdx.x == 0) {
        #pragma unroll
        for (int i = 0; i < 7; i++) MBAR_INVAL(sb + 16 + 8 * i);
    }
    __syncthreads();
    if ((threadIdx.x >> 5) == 0) TC_DEALLOC(tmem, 256);
#endif
}

// ---------------- GEMM -> images (outmode 1: normal, 2: V transposed) ----------------
__device__ __forceinline__ void gemm_body_img(const unsigned char* __restrict__ Aimg,
                                              const __nv_bfloat16* __restrict__ Wp,
                                              const float* __restrict__ bias,
                                              unsigned char* __restrict__ Cimg,
                                              int tile, int epi, int outmode) {
#if defined(__CUDA_ARCH_FEAT_SM103_ALL)
    extern __shared__ char smem[];
    uint32_t sb = smem_u32(smem);
    int tid = threadIdx.x, wid = tid >> 5, lane = tid & 31;
    uint32_t tmem = tc_gemm_start(sb);
    tc_gemm_mainloop<2>(Aimg, Wp, tile, sb, tmem);

    int sp = wid & 3, hf = wid >> 2;
    int rr = sp * 32 + lane;
    for (int p = hf * 4; p < hf * 4 + 4; p++) {
        uint32_t regs[32];
        TC_LD_X32(regs, tmem + p * 32);
        TC_WAIT_LD();
        float v[32];
        #pragma unroll
        for (int j = 0; j < 32; j++) {
            float u = __uint_as_float(regs[j]);
            if (epi >= 1) u += bias[p * 32 + j];
            if (epi == 2) u = gelu_tanh(u);
            v[j] = u;
        }
        if (outmode == 1) {
            unsigned char* hi = Cimg + img_off(tile, p >> 1, 0);
            unsigned char* lo = Cimg + img_off(tile, p >> 1, 1);
            int cb = (p & 1) * 32;
            #pragma unroll
            for (int j = 0; j < 32; j += 2) {
                uint32_t off = rr * 128 + (cb + j) * 2;
                off ^= (off >> 3) & 0x70;
                uint32_t hw, lw;
                packhilo(v[j], v[j + 1], hw, lw);
                *(uint32_t*)(hi + off) = hw;
                *(uint32_t*)(lo + off) = lw;
            }
        } else {
            int kv = rr & 63, half = rr >> 6;
            unsigned char* hi = Cimg + imgv_off(tile, p >> 1, half, 0);
            unsigned char* lo = Cimg + imgv_off(tile, p >> 1, half, 1);
            #pragma unroll
            for (int j = 0; j < 32; j++) {
                int dd = (p & 1) * 32 + j;
                uint32_t off = dd * 128 + kv * 2;
                off ^= (off >> 3) & 0x70;
                *(unsigned short*)(hi + off) = f2bf(v[j]);
                *(unsigned short*)(lo + off) = f2bf_lo(v[j]);
            }
        }
    }
    tc_gemm_end(sb, tmem);
#endif
}

// merged QKV: grid = 128 + 256 + 256  (2-stage, 2 CTAs/SM)
__global__ __launch_bounds__(256, 2)
void qkv_tc_kernel(const unsigned char* __restrict__ qnImg,
                   const unsigned char* __restrict__ knImg,
                   const __nv_bfloat16* __restrict__ wprep,
                   unsigned char* __restrict__ imgQ,
                   unsigned char* __restrict__ imgK,
                   unsigned char* __restrict__ imgVt) {
    const size_t WCH = (size_t)12 * 256 * 64;
    int bx = blockIdx.x;
    if (bx < 128)
        gemm_body_img(qnImg, wprep + 0 * WCH, nullptr, imgQ, bx, 0, 1);
    else if (bx < 384)
        gemm_body_img(knImg, wprep + 1 * WCH, nullptr, imgK, bx - 128, 0, 1);
    else
        gemm_body_img(knImg, wprep + 2 * WCH, nullptr, imgVt, bx - 384, 0, 2);
}

// ffn1: gelu epilogue -> images  (2-stage, 2 CTAs/SM)
__global__ __launch_bounds__(256, 2)
void ffn1_tc_kernel(const unsigned char* __restrict__ Aimg,
                    const __nv_bfloat16* __restrict__ Wp,
                    const float* __restrict__ bias,
                    unsigned char* __restrict__ Cimg) {
    gemm_body_img(Aimg, Wp, bias, Cimg, blockIdx.x, 2, 1);
}

// ---------------- Wo GEMM + inner LN fused (3-stage, big epilogue stage) ----------------
__global__ __launch_bounds__(256)
void wo_ln_kernel(const unsigned char* __restrict__ Aimg,
                  const __nv_bfloat16* __restrict__ Wp,
                  const float* __restrict__ in_s, const float* __restrict__ in_b,
                  float* __restrict__ hOut, unsigned char* __restrict__ hImg) {
#if defined(__CUDA_ARCH_FEAT_SM103_ALL)
    extern __shared__ char smem[];
    uint32_t sb = smem_u32(smem);
    int tid = threadIdx.x, wid = tid >> 5, lane = tid & 31;
    int tile = blockIdx.x;
    uint32_t tmem = tc_gemm_start(sb);
    tc_gemm_mainloop<3>(Aimg, Wp, tile, sb, tmem);

    float* stage = (float*)(smem + 1024);            // [128][257]
    float* redS  = (float*)(smem + 1024 + 131584);   // [128][4]
    int sp = wid & 3, hf = wid >> 2;
    int rr = sp * 32 + lane;
    float psum = 0.f, psq = 0.f;
    for (int p = hf * 4; p < hf * 4 + 4; p++) {
        uint32_t regs[32];
        TC_LD_X32(regs, tmem + p * 32);
        TC_WAIT_LD();
        #pragma unroll
        for (int j = 0; j < 32; j++) {
            float v = __uint_as_float(regs[j]);
            psum += v; psq += v * v;
            stage[rr * 257 + p * 32 + j] = v;
        }
    }
    redS[rr * 4 + hf * 2] = psum;
    redS[rr * 4 + hf * 2 + 1] = psq;
    __syncthreads();
    float m = (redS[rr * 4] + redS[rr * 4 + 2]) * (1.0f / Dm);
    float var = (redS[rr * 4 + 1] + redS[rr * 4 + 3]) * (1.0f / Dm) - m * m;
    float rs = rsqrtf(fmaxf(var, 0.f) + 1e-5f);
    int row = tile * 128 + rr;
    for (int p = hf * 4; p < hf * 4 + 4; p++) {
        float y[32];
        #pragma unroll
        for (int j = 0; j < 32; j++) {
            int col = p * 32 + j;
            y[j] = (stage[rr * 257 + col] - m) * rs * in_s[col] + in_b[col];
        }
        #pragma unroll
        for (int j = 0; j < 32; j += 4)
            *(float4*)&hOut[(size_t)row * Dm + p * 32 + j] =
                make_float4(y[j], y[j + 1], y[j + 2], y[j + 3]);
        unsigned char* hi = hImg + img_off(tile, p >> 1, 0);
        unsigned char* lo = hImg + img_off(tile, p >> 1, 1);
        int cb = (p & 1) * 32;
        #pragma unroll
        for (int j = 0; j < 32; j += 2) {
            uint32_t off = rr * 128 + (cb + j) * 2;
            off ^= (off >> 3) & 0x70;
            uint32_t hw, lw;
            packhilo(y[j], y[j + 1], hw, lw);
            *(uint32_t*)(hi + off) = hw;
            *(uint32_t*)(lo + off) = lw;
        }
    }
    tc_gemm_end(sb, tmem);
#endif
}

// ---------------- ffn2 GEMM + residual + double LN + scatter fused ----------------
__global__ __launch_bounds__(256)
void ffn2_scatter_kernel(const unsigned char* __restrict__ Aimg,
                         const __nv_bfloat16* __restrict__ Wp,
                         const float* __restrict__ b2,
                         const float* __restrict__ hBuf,
                         const int* __restrict__ qi,
                         const float* __restrict__ os, const float* __restrict__ ob,
                         const float* __restrict__ es, const float* __restrict__ eb,
                         float* __restrict__ upd, float* __restrict__ out) {
#if defined(__CUDA_ARCH_FEAT_SM103_ALL)
    extern __shared__ char smem[];
    uint32_t sb = smem_u32(smem);
    int tid = threadIdx.x, wid = tid >> 5, lane = tid & 31;
    int tile = blockIdx.x;
    uint32_t tmem = tc_gemm_start(sb);
    tc_gemm_mainloop<3>(Aimg, Wp, tile, sb, tmem);

    float* stage = (float*)(smem + 1024);                      // [128][257]
    float* redS  = (float*)(smem + 1024 + 131584);             // [128][4]
    float* rm2   = (float*)(smem + 1024 + 131584 + 2048);      // [128]
    float* rr2   = rm2 + 128;                                  // [128]
    unsigned long long* rowbase = (unsigned long long*)(rr2 + 128);  // [128]

    int sp = wid & 3, hf = wid >> 2;
    int rr = sp * 32 + lane;
    int row = tile * 128 + rr;

    float psum = 0.f, psq = 0.f;
    for (int p = hf * 4; p < hf * 4 + 4; p++) {
        uint32_t regs[32];
        TC_LD_X32(regs, tmem + p * 32);
        TC_WAIT_LD();
        #pragma unroll
        for (int j = 0; j < 32; j += 4) {
            float4 hv = *(const float4*)&hBuf[(size_t)row * Dm + p * 32 + j];
            float x0 = __uint_as_float(regs[j])     + b2[p * 32 + j]     + hv.x;
            float x1 = __uint_as_float(regs[j + 1]) + b2[p * 32 + j + 1] + hv.y;
            float x2 = __uint_as_float(regs[j + 2]) + b2[p * 32 + j + 2] + hv.z;
            float x3 = __uint_as_float(regs[j + 3]) + b2[p * 32 + j + 3] + hv.w;
            psum += x0 + x1 + x2 + x3;
            psq  += x0 * x0 + x1 * x1 + x2 * x2 + x3 * x3;
            stage[rr * 257 + p * 32 + j]     = x0;
            stage[rr * 257 + p * 32 + j + 1] = x1;
            stage[rr * 257 + p * 32 + j + 2] = x2;
            stage[rr * 257 + p * 32 + j + 3] = x3;
        }
    }
    redS[rr * 4 + hf * 2] = psum;
    redS[rr * 4 + hf * 2 + 1] = psq;
    if (tid < 128) {
        int g = tile * 128 + tid;
        int b = g >> 9, r = g & 511;
        rowbase[tid] = ((unsigned long long)b * NS + qi[r]) * Dm;
    }
    __syncthreads();
    float m1 = (redS[rr * 4] + redS[rr * 4 + 2]) * (1.0f / Dm);
    float v1 = (redS[rr * 4 + 1] + redS[rr * 4 + 3]) * (1.0f / Dm) - m1 * m1;
    float rs1 = rsqrtf(fmaxf(v1, 0.f) + 1e-5f);
    __syncthreads();

    float psum2 = 0.f, psq2 = 0.f;
    for (int p = hf * 4; p < hf * 4 + 4; p++) {
        #pragma unroll
        for (int j = 0; j < 32; j++) {
            int col = p * 32 + j;
            float y = (stage[rr * 257 + col] - m1) * rs1 * os[col] + ob[col];
            stage[rr * 257 + col] = y;
            psum2 += y; psq2 += y * y;
        }
    }
    __syncthreads();
    redS[rr * 4 + hf * 2] = psum2;
    redS[rr * 4 + hf * 2 + 1] = psq2;
    __syncthreads();
    if (hf == 0) {
        float m2 = (redS[rr * 4] + redS[rr * 4 + 2]) * (1.0f / Dm);
        float v2 = (redS[rr * 4 + 1] + redS[rr * 4 + 3]) * (1.0f / Dm) - m2 * m2;
        rm2[rr] = m2;
        rr2[rr] = rsqrtf(fmaxf(v2, 0.f) + 1e-5f);
    }
    __syncthreads();

    float est = es[tid], ebt = eb[tid];
    for (int i = 0; i < 128; i++) {
        float y = stage[i * 257 + tid];
        float res = (y - rm2[i]) * rr2[i] * est + ebt;
        unsigned long long o = rowbase[i] + tid;
        atomicAdd(&upd[o], res);
        atomicAdd(&out[o], res);
    }
    tc_gemm_end(sb, tmem);
#endif
}

// ---------------- tc flash attention ----------------
__global__ __launch_bounds__(256, 2)
void attn_tc_kernel(const unsigned char* __restrict__ Qimg,
                    const unsigned char* __restrict__ Kimg,
                    const unsigned char* __restrict__ Vimg,
                    const uint32_t* __restrict__ mbits,
                    unsigned char* __restrict__ ctxImg) {
#if defined(__CUDA_ARCH_FEAT_SM103_ALL)
    extern __shared__ char smem[];
    uint32_t sb = smem_u32(smem);
    int qt = blockIdx.x, h = blockIdx.y, b = blockIdx.z;
    int tid = threadIdx.x, wid = tid >> 5, lane = tid & 31;
    int sp = wid & 3, hf = wid >> 2;
    float* redA = (float*)(smem + 64);
    float* redB = (float*)(smem + 64 + 512);

    if (wid == 0) { TC_ALLOC(sb + 0, 256); TC_RELINQ(); }
    if (tid == 0) {
        MBAR_INIT(sb + 16, 1);
        MBAR_INIT(sb + 24, 1);
        MBAR_INIT(sb + 32, 1);
        MBAR_INIT(sb + 40, 1);
        MBAR_INIT(sb + 48, 1);
    }
    __syncthreads();
    uint32_t tmem;
    asm volatile("ld.shared.b32 %0, [%1];" : "=r"(tmem) : "r"(sb + 0));

    auto issueK = [&](int t) {
        int kt = b * 8 + t;
        MBAR_EXPECT(sb + 32, 32768);
        bulk_cp(sb + AT_KHI, Kimg + img_off(kt, h, 0), 16384, sb + 32);
        bulk_cp(sb + AT_KLO, Kimg + img_off(kt, h, 1), 16384, sb + 32);
    };
    auto issueV = [&](int t) {
        int kt = b * 8 + t;
        MBAR_EXPECT(sb + 40, 32768);
        bulk_cp(sb + AT_VHI_A, Vimg + imgv_off(kt, h, 0, 0), 8192, sb + 40);
        bulk_cp(sb + AT_VHI_B, Vimg + imgv_off(kt, h, 1, 0), 8192, sb + 40);
        bulk_cp(sb + AT_VLO_A, Vimg + imgv_off(kt, h, 0, 1), 8192, sb + 40);
        bulk_cp(sb + AT_VLO_B, Vimg + imgv_off(kt, h, 1, 1), 8192, sb + 40);
    };
    if (tid == 0) {
        MBAR_EXPECT(sb + 48, 32768);
        bulk_cp(sb + AT_QHI, Qimg + img_off(b * 4 + qt, h, 0), 16384, sb + 48);
        bulk_cp(sb + AT_QLO, Qimg + img_off(b * 4 + qt, h, 1), 16384, sb + 48);
        issueK(0);
        issueV(0);
    }

    int qrow = sp * 32 + lane;
    const uint32_t* rowbits = mbits + (size_t)(qt * 128 + qrow) * 32 + hf * 2;
    float mrow = -1e30f, lrow = 0.f;
    float acc[32];
    #pragma unroll
    for (int j = 0; j < 32; j++) acc[j] = 0.f;

    int ph1 = 0, ph2 = 0, kph = 0, vph = 0;

    for (int t = 0; t < 8; t++) {
        int k0 = t * 128;
        if (tid == 0) {
            if (t == 0) MBAR_WAIT(sb + 48, 0);
            MBAR_WAIT(sb + 32, kph);
            uint64_t qhiD = make_desc(sb + AT_QHI);
            uint64_t qloD = make_desc(sb + AT_QLO);
            uint64_t khiD = make_desc(sb + AT_KHI);
            uint64_t kloD = make_desc(sb + AT_KLO);
            bool first = true;
            #pragma unroll
            for (int k = 0; k < 4; k++) { mma_f16_ss(tmem, qhiD + 2 * k, khiD + 2 * k, IDESC_N128, !first); first = false; }
            #pragma unroll
            for (int k = 0; k < 4; k++) mma_f16_ss(tmem, qloD + 2 * k, khiD + 2 * k, IDESC_N128, true);
            #pragma unroll
            for (int k = 0; k < 4; k++) mma_f16_ss(tmem, qhiD + 2 * k, kloD + 2 * k, IDESC_N128, true);
            TC_COMMIT(sb + 16);
        }
        kph ^= 1;
        MBAR_WAIT(sb + 16, ph1); ph1 ^= 1;
        TC_FENCE_AFTER();
        if (tid == 0 && t < 7) issueK(t + 1);

        uint32_t sr[32];
        float s[64];
        TC_LD_X32(sr, tmem + hf * 64);
        TC_WAIT_LD();
        uint32_t w0 = rowbits[(k0 >> 5)];
        #pragma unroll
        for (int j = 0; j < 32; j++)
            s[j] = ((w0 >> j) & 1u) ? __uint_as_float(sr[j]) * ATT_SCALE : -1e9f;
        TC_LD_X32(sr, tmem + hf * 64 + 32);
        TC_WAIT_LD();
        uint32_t w1 = rowbits[(k0 >> 5) + 1];
        #pragma unroll
        for (int j = 0; j < 32; j++)
            s[32 + j] = ((w1 >> j) & 1u) ? __uint_as_float(sr[j]) * ATT_SCALE : -1e9f;

        float mloc = -1e30f;
        #pragma unroll
        for (int j = 0; j < 64; j++) mloc = fmaxf(mloc, s[j]);
        (hf ? redB : redA)[qrow] = mloc;
        __syncthreads();
        float mx = fmaxf(redA[qrow], redB[qrow]);
        float mnew = fmaxf(mrow, mx);
        float alpha = __expf(mrow - mnew);
        mrow = mnew;
        __syncthreads();
        float ps = 0.f;
        #pragma unroll
        for (int j = 0; j < 64; j++) {
            float p = __expf(s[j] - mnew);
            s[j] = p;
            ps += p;
        }
        (hf ? redB : redA)[qrow] = ps;
        __syncthreads();
        lrow = lrow * alpha + redA[qrow] + redB[qrow];

        uint32_t woff = (uint32_t)sp << 21;
        uint32_t pv[32];
        #pragma unroll
        for (int c = 0; c < 32; c++) CVT2(pv[c], s[2 * c], s[2 * c + 1]);
        TC_ST_X32(tmem + hf * 32 + woff, pv);
        #pragma unroll
        for (int c = 0; c < 32; c++) {
            float h0 = __uint_as_float(pv[c] << 16);
            float h1 = __uint_as_float(pv[c] & 0xFFFF0000u);
            CVT2(pv[c], s[2 * c] - h0, s[2 * c + 1] - h1);
        }
        TC_ST_X32(tmem + 64 + hf * 32 + woff, pv);
        TC_WAIT_ST();
        TC_FENCE_BEFORE();
        __syncthreads();

        if (tid == 0) {
            MBAR_WAIT(sb + 40, vph);
            TC_FENCE_AFTER();
            uint64_t vhiA = make_desc(sb + AT_VHI_A);
            uint64_t vhiB = make_desc(sb + AT_VHI_B);
            uint64_t vloA = make_desc(sb + AT_VLO_A);
            uint64_t vloB = make_desc(sb + AT_VLO_B);
            bool first = true;
            #pragma unroll
            for (int s8 = 0; s8 < 8; s8++) {
                uint64_t bd = (s8 < 4 ? vhiA + 2 * s8 : vhiB + 2 * (s8 - 4));
                mma_f16_ts(tmem + 128, tmem + 0 + s8 * 8, bd, IDESC_N64, !first);
                first = false;
            }
            #pragma unroll
            for (int s8 = 0; s8 < 8; s8++) {
                uint64_t bd = (s8 < 4 ? vhiA + 2 * s8 : vhiB + 2 * (s8 - 4));
                mma_f16_ts(tmem + 128, tmem + 64 + s8 * 8, bd, IDESC_N64, true);
            }
            #pragma unroll
            for (int s8 = 0; s8 < 8; s8++) {
                uint64_t bd = (s8 < 4 ? vloA + 2 * s8 : vloB + 2 * (s8 - 4));
                mma_f16_ts(tmem + 128, tmem + 0 + s8 * 8, bd, IDESC_N64, true);
            }
            TC_COMMIT(sb + 24);
        }
        vph ^= 1;
        MBAR_WAIT(sb + 24, ph2); ph2 ^= 1;
        TC_FENCE_AFTER();
        if (tid == 0 && t < 7) issueV(t + 1);

        uint32_t dr[32];
        TC_LD_X32(dr, tmem + 128 + hf * 32);
        TC_WAIT_LD();
        TC_FENCE_BEFORE();
        #pragma unroll
        for (int j = 0; j < 32; j++)
            acc[j] = acc[j] * alpha + __uint_as_float(dr[j]);
    }

    {
        float invl = 1.0f / lrow;
        unsigned char* chi = ctxImg + img_off(b * 4 + qt, h, 0);
        unsigned char* clo = ctxImg + img_off(b * 4 + qt, h, 1);
        #pragma unroll
        for (int j = 0; j < 32; j += 2) {
            float v0 = acc[j] * invl, v1 = acc[j + 1] * invl;
            uint32_t off = qrow * 128 + (hf * 32 + j) * 2;
            off ^= (off >> 3) & 0x70;
            uint32_t hw, lw;
            packhilo(v0, v1, hw, lw);
            *(uint32_t*)(chi + off) = hw;
            *(uint32_t*)(clo + off) = lw;
        }
    }

    __syncthreads();
    if (tid == 0) {
        MBAR_INVAL(sb + 16); MBAR_INVAL(sb + 24); MBAR_INVAL(sb + 32);
        MBAR_INVAL(sb + 40); MBAR_INVAL(sb + 48);
    }
    __syncthreads();
    if (wid == 0) TC_DEALLOC(tmem, 256);
#endif
}

// ---------------- host launcher ----------------
extern "C" void kernel_launch(void* const* d_in, const int* in_sizes, int n_in,
                              void* d_out, int out_size) {
    const float* update = (const float*)d_in[0];
    const float* emb    = (const float*)d_in[1];
    const float* mask   = (const float*)d_in[2];
    const float* Wq     = (const float*)d_in[3];
    const float* Wk     = (const float*)d_in[4];
    const float* Wv     = (const float*)d_in[5];
    const float* Wo     = (const float*)d_in[6];
    const float* W1     = (const float*)d_in[7];
    const float* b1     = (const float*)d_in[8];
    const float* W2     = (const float*)d_in[9];
    const float* b2     = (const float*)d_in[10];
    const float* sys_s  = (const float*)d_in[11];
    const float* sys_b  = (const float*)d_in[12];
    const float* eff_s  = (const float*)d_in[13];
    const float* eff_b  = (const float*)d_in[14];
    const float* in_s   = (const float*)d_in[15];
    const float* in_b   = (const float*)d_in[16];
    const float* out_s  = (const float*)d_in[17];
    const float* out_b  = (const float*)d_in[18];
    const int*   qidx   = (const int*)d_in[19];
    const int*   kidx   = (const int*)d_in[20];
    float* out = (float*)d_out;

    float *p_upd, *p_h;
    uint32_t* p_mb;
    __nv_bfloat16* p_w;
    unsigned char *p_iqn, *p_ikn, *p_iQ, *p_iK, *p_iVt, *p_ictx, *p_ih, *p_it;
    cudaGetSymbolAddress((void**)&p_upd, g_upd);
    cudaGetSymbolAddress((void**)&p_h,   g_h);
    cudaGetSymbolAddress((void**)&p_mb,  g_mbits);
    cudaGetSymbolAddress((void**)&p_w,   g_wprep);
    cudaGetSymbolAddress((void**)&p_iqn, g_img_qn);
    cudaGetSymbolAddress((void**)&p_ikn, g_img_kn);
    cudaGetSymbolAddress((void**)&p_iQ,  g_img_Q);
    cudaGetSymbolAddress((void**)&p_iK,  g_img_K);
    cudaGetSymbolAddress((void**)&p_iVt, g_img_Vt);
    cudaGetSymbolAddress((void**)&p_ictx, g_img_ctx);
    cudaGetSymbolAddress((void**)&p_ih,  g_img_h);
    cudaGetSymbolAddress((void**)&p_it,  g_img_t);

    cudaFuncSetAttribute(qkv_tc_kernel, cudaFuncAttributeMaxDynamicSharedMemorySize, GT2_SMEM_TOTAL);
    cudaFuncSetAttribute(ffn1_tc_kernel, cudaFuncAttributeMaxDynamicSharedMemorySize, GT2_SMEM_TOTAL);
    cudaFuncSetAttribute(wo_ln_kernel, cudaFuncAttributeMaxDynamicSharedMemorySize, GT_SMEM_TOTAL);
    cudaFuncSetAttribute(ffn2_scatter_kernel, cudaFuncAttributeMaxDynamicSharedMemorySize, GT_SMEM_TOTAL);
    cudaFuncSetAttribute(attn_tc_kernel, cudaFuncAttributeMaxDynamicSharedMemorySize, AT_SMEM_TOTAL);

    const size_t WCH = (size_t)12 * 256 * 64;

    cudaMemsetAsync(d_out, 0, (size_t)out_size * sizeof(float), 0);
    cudaMemcpyAsync(p_upd, update, (size_t)Bz * NS * Dm * sizeof(float),
                    cudaMemcpyDeviceToDevice, 0);

    prep_all_kernel<<<72 + Ll * 64, 256>>>(Wq, Wk, Wv, Wo, W1, W2, p_w, mask, p_mb);

    for (int l = 0; l < Ll; l++) {
        const int* qi = qidx + l * NQ;
        const int* ki = kidx + l * NK;
        const uint32_t* mb = p_mb + (size_t)l * NQ * (NK / 32);

        gather_ln_img_kernel<<<(Bz * (NQ + NK)) / 8, 256>>>(emb, p_upd, qi, ki,
                                                            sys_s, sys_b, p_iqn, p_ikn);

        qkv_tc_kernel<<<640, 256, GT2_SMEM_TOTAL>>>(p_iqn, p_ikn, p_w, p_iQ, p_iK, p_iVt);

        attn_tc_kernel<<<dim3(NQ / 128, Hh, Bz), 256, AT_SMEM_TOTAL>>>(p_iQ, p_iK, p_iVt, mb, p_ictx);

        wo_ln_kernel<<<128, 256, GT_SMEM_TOTAL>>>(p_ictx, p_w + 3 * WCH, in_s, in_b, p_h, p_ih);

        ffn1_tc_kernel<<<128, 256, GT2_SMEM_TOTAL>>>(p_ih, p_w + 4 * WCH, b1, p_it);

        ffn2_scatter_kernel<<<128, 256, GT_SMEM_TOTAL>>>(p_it, p_w + 5 * WCH, b2, p_h, qi,
                                                         out_s, out_b, eff_s, eff_b,
                                                         p_upd, out);
    }
}